// round 6
// baseline (speedup 1.0000x reference)
#include <cuda_runtime.h>
#include <cstdint>
#include <math.h>

#define BB 512
#define MM 4096
#define DD 64
#define CC 256
#define NT 256                    // threads per block (8 warps)
#define NW (NT / 32)
#define TILE 64                   // memory rows per tile (16 KB data)
#define NTILES (MM / TILE)        // 64
#define ROWPAD 17                 // float4 per padded row (16 data + 1 pad)
#define BUFF4 (TILE * ROWPAD)     // float4 per buffer = 1088
#define LD_PER_THR (TILE * (DD/4) / NT)   // 4
#define RPT (MM / NT)             // 16
#define EPSF 1e-8f
#define LOG2E 1.442695040888963f

// dyn smem floats: stream buffers (SB aliased inside) + SA + misc  (~52.5 KB)
#define SMEM_FLOATS (2 * BUFF4 * 4 + MM + CC + DD + 8 + 6 + 6)
#define SMEM_BYTES (SMEM_FLOATS * 4)

// ---- software exp2: FADD/FMA only ----
__device__ __forceinline__ float fast_exp2(float y) {
    y = fmaxf(y, -250.0f);
    float t = y + 12582912.0f;
    int   ni = __float_as_int(t) - 0x4B400000;
    float f = y - (t - 12582912.0f);
    float p = 1.52527338e-5f;
    p = fmaf(p, f, 1.54035304e-4f);
    p = fmaf(p, f, 1.33335581e-3f);
    p = fmaf(p, f, 9.61812911e-3f);
    p = fmaf(p, f, 5.55041087e-2f);
    p = fmaf(p, f, 2.40226507e-1f);
    p = fmaf(p, f, 6.93147181e-1f);
    p = fmaf(p, f, 1.0f);
    int n1 = ni >> 1;
    int n2 = ni - n1;
    float s1 = __int_as_float((n1 + 127) << 23);
    float s2 = __int_as_float((n2 + 127) << 23);
    return p * s1 * s2;
}

__device__ __forceinline__ float fast_log2(float x) {
    int ix = __float_as_int(x);
    int e = ((ix >> 23) & 0xff) - 127;
    float m = __int_as_float((ix & 0x007fffff) | 0x3f800000);
    if (m > 1.41421356f) { m *= 0.5f; e += 1; }
    float s = __fdividef(m - 1.0f, m + 1.0f);
    float s2 = s * s;
    float p = 0.111111111f;
    p = fmaf(p, s2, 0.142857143f);
    p = fmaf(p, s2, 0.2f);
    p = fmaf(p, s2, 0.333333333f);
    p = fmaf(p, s2, 1.0f);
    float lnm = 2.0f * s * p;
    return (float)e + lnm * LOG2E;
}

__device__ __forceinline__ float fast_exp(float z) { return fast_exp2(z * LOG2E); }
__device__ __forceinline__ float fast_pow(float x, float g) { return fast_exp2(g * fast_log2(x)); }

__device__ __forceinline__ float blockReduceSum(float v, float* sh) {
    int lane = threadIdx.x & 31, wid = threadIdx.x >> 5;
    #pragma unroll
    for (int o = 16; o; o >>= 1) v += __shfl_xor_sync(0xffffffffu, v, o);
    __syncthreads();
    if (lane == 0) sh[wid] = v;
    __syncthreads();
    if (wid == 0) {
        float x = (lane < NW) ? sh[lane] : 0.0f;
        #pragma unroll
        for (int o = NW / 2; o; o >>= 1) x += __shfl_xor_sync(0xffffffffu, x, o);
        if (lane == 0) sh[0] = x;
    }
    __syncthreads();
    return sh[0];
}

__device__ __forceinline__ float blockReduceMax(float v, float* sh) {
    int lane = threadIdx.x & 31, wid = threadIdx.x >> 5;
    #pragma unroll
    for (int o = 16; o; o >>= 1) v = fmaxf(v, __shfl_xor_sync(0xffffffffu, v, o));
    __syncthreads();
    if (lane == 0) sh[wid] = v;
    __syncthreads();
    if (wid == 0) {
        float x = (lane < NW) ? sh[lane] : -INFINITY;
        #pragma unroll
        for (int o = NW / 2; o; o >>= 1) x = fmaxf(x, __shfl_xor_sync(0xffffffffu, x, o));
        if (lane == 0) sh[0] = x;
    }
    __syncthreads();
    return sh[0];
}

__device__ __forceinline__ void prefetch_tile(const float4* gsrc_tile,
                                              uint32_t dst_base_u32, int tid) {
    #pragma unroll
    for (int k = 0; k < LD_PER_THR; k++) {
        int lin = tid + k * NT;             // 0..1023, coalesced
        int r = lin >> 4;
        int c = lin & 15;
        uint32_t dst = dst_base_u32 + (uint32_t)(r * ROWPAD + c) * 16u;
        asm volatile("cp.async.cg.shared.global [%0], [%1], 16;\n"
                     :: "r"(dst), "l"(gsrc_tile + lin) : "memory");
    }
    asm volatile("cp.async.commit_group;\n" ::: "memory");
}

__global__ __launch_bounds__(NT, 4)
void ntm_head_kernel(
    const float* __restrict__ memory,     // (B, M, D)
    const float* __restrict__ cstate,     // (B, C)
    const float* __restrict__ prevw,      // (B, M)
    const float* __restrict__ Wk,         // (C, D)
    const float* __restrict__ Wb,
    const float* __restrict__ bb,
    const float* __restrict__ Wgate,
    const float* __restrict__ bgate,
    const float* __restrict__ Ws,
    const float* __restrict__ bs,
    const float* __restrict__ Wg,
    const float* __restrict__ bg,
    float* __restrict__ out)              // (B, M)
{
    extern __shared__ float smem[];
    float4* buf     = reinterpret_cast<float4*>(smem);      // 2 * BUFF4
    float*  SB      = smem;                                  // alias: epilogue only
    float*  SA      = smem + 2 * BUFF4 * 4;                 // MM
    float*  sh_cs   = SA + MM;                              // CC
    float*  sh_qn   = sh_cs + CC;                           // DD
    float*  sh_red  = sh_qn + DD;                           // 8
    float*  sh_scal = sh_red + 8;                           // 6
    float*  sh_par  = sh_scal + 6;

    const int b    = blockIdx.x;
    const int tid  = threadIdx.x;
    const int lane = tid & 31;
    const int wid  = tid >> 5;

    const uint32_t buf_u32 = (uint32_t)__cvta_generic_to_shared(buf);
    const float4* mem4 = reinterpret_cast<const float4*>(memory)
                       + (size_t)b * MM * (DD / 4);

    // kick off tile 0 immediately
    prefetch_tile(mem4, buf_u32, tid);

    // controller preamble (overlaps tile-0 DMA)
    sh_cs[tid] = cstate[(size_t)b * CC + tid];
    __syncthreads();

    if (tid < DD) {
        float acc = 0.0f;
        #pragma unroll 8
        for (int c = 0; c < CC; c++) acc = fmaf(sh_cs[c], Wk[c * DD + tid], acc);
        sh_qn[tid] = acc;
    }
    if (wid >= 2) {
        int s = wid - 2;
        float acc = 0.0f;
        if (s < 3) {
            const float* W = (s == 0) ? Wb : (s == 1) ? Wgate : Wg;
            for (int c = lane; c < CC; c += 32) acc = fmaf(sh_cs[c], W[c], acc);
        } else {
            int col = s - 3;
            for (int c = lane; c < CC; c += 32) acc = fmaf(sh_cs[c], Ws[c * 3 + col], acc);
        }
        #pragma unroll
        for (int o = 16; o; o >>= 1) acc += __shfl_xor_sync(0xffffffffu, acc, o);
        if (lane == 0) sh_scal[s] = acc;
    }
    __syncthreads();

    if (wid == 0) {
        float a = sh_qn[lane], c = sh_qn[lane + 32];
        float v = a * a + c * c;
        #pragma unroll
        for (int o = 16; o; o >>= 1) v += __shfl_xor_sync(0xffffffffu, v, o);
        float inv = 1.0f / (sqrtf(v) + EPSF);
        sh_qn[lane]      = a * inv;
        sh_qn[lane + 32] = c * inv;
    }
    if (tid == 32) {
        sh_par[0] = log1pf(__expf(sh_scal[0] + bb[0])) + 1.0f;             // beta
        sh_par[1] = 1.0f / (1.0f + __expf(-(sh_scal[1] + bgate[0])));      // gate
        sh_par[2] = log1pf(__expf(sh_scal[2] + bg[0])) + 1.0f;             // gamma
        float a0 = sh_scal[3] + bs[0];
        float a1 = sh_scal[4] + bs[1];
        float a2 = sh_scal[5] + bs[2];
        float mx = fmaxf(a0, fmaxf(a1, a2));
        float e0 = __expf(a0 - mx), e1 = __expf(a1 - mx), e2 = __expf(a2 - mx);
        float inv = 1.0f / (e0 + e1 + e2);
        sh_par[3] = e0 * inv; sh_par[4] = e1 * inv; sh_par[5] = e2 * inv;
    }
    __syncthreads();

    // ================= main streaming loop: cp.async double buffer =================
    const float4* qn4 = reinterpret_cast<const float4*>(sh_qn);

    for (int t = 0; t < NTILES; t++) {
        if (t + 1 < NTILES) {
            prefetch_tile(mem4 + (size_t)(t + 1) * TILE * (DD / 4),
                          buf_u32 + (uint32_t)(((t + 1) & 1) * BUFF4) * 16u, tid);
            asm volatile("cp.async.wait_group 1;\n" ::: "memory");
        } else {
            asm volatile("cp.async.wait_group 0;\n" ::: "memory");
        }
        __syncthreads();

        if (tid < TILE) {
            const float4* rowp = buf + (size_t)(t & 1) * BUFF4 + tid * ROWPAD;
            float dot = 0.0f, ss = 0.0f;
            #pragma unroll
            for (int j = 0; j < DD / 4; j++) {
                float4 v = rowp[j];
                float4 q = qn4[j];
                dot = fmaf(v.x, q.x, dot); dot = fmaf(v.y, q.y, dot);
                dot = fmaf(v.z, q.z, dot); dot = fmaf(v.w, q.w, dot);
                ss  = fmaf(v.x, v.x, ss);  ss  = fmaf(v.y, v.y, ss);
                ss  = fmaf(v.z, v.z, ss);  ss  = fmaf(v.w, v.w, ss);
            }
            SA[t * TILE + tid] = dot * rsqrtf(ss);
        }
        __syncthreads();
    }

    // ================= softmax(beta * sim) over M =================
    const float beta = sh_par[0];
    float lmax = -INFINITY;
    #pragma unroll
    for (int k = 0; k < RPT; k++) lmax = fmaxf(lmax, SA[tid + k * NT]);
    const float smax = blockReduceMax(lmax, sh_red) * beta;

    float lsum = 0.0f;
    #pragma unroll
    for (int k = 0; k < RPT; k++) {
        int m = tid + k * NT;
        float e = fast_exp(fmaf(beta, SA[m], -smax));
        SA[m] = e;
        lsum += e;
    }
    const float invsum = 1.0f / blockReduceSum(lsum, sh_red);

    // ---- gate interpolation (in place) ----
    const float gate = sh_par[1], gate1 = 1.0f - sh_par[1];
    const float* pw = prevw + (size_t)b * MM;
    #pragma unroll
    for (int k = 0; k < RPT; k++) {
        int m = tid + k * NT;
        SA[m] = fmaf(gate, SA[m] * invsum, gate1 * pw[m]);
    }
    __syncthreads();

    // ================= circular 3-tap shift + sharpening =================
    const float gamma = sh_par[2];
    const float s0 = sh_par[3], s1 = sh_par[4], s2 = sh_par[5];
    float psum = 0.0f;
    #pragma unroll
    for (int k = 0; k < RPT; k++) {
        int m  = tid + k * NT;
        int ml = (m == 0)      ? MM - 1 : m - 1;
        int mr = (m == MM - 1) ? 0      : m + 1;
        float sv = SA[ml] * s0 + SA[m] * s1 + SA[mr] * s2;
        float p = fast_pow(sv + EPSF, gamma);
        SB[m] = p;
        psum += p;
    }
    psum = blockReduceSum(psum, sh_red);   // internal barrier fences SB
    const float invp = 1.0f / (psum + EPSF);

    float* ob = out + (size_t)b * MM;
    #pragma unroll
    for (int k = 0; k < RPT; k++) {
        int m = tid + k * NT;
        ob[m] = SB[m] * invp;
    }
}

extern "C" void kernel_launch(void* const* d_in, const int* in_sizes, int n_in,
                              void* d_out, int out_size) {
    const float* memory = (const float*)d_in[0];
    const float* cstate = (const float*)d_in[1];
    const float* prevw  = (const float*)d_in[2];
    const float* Wk     = (const float*)d_in[3];
    const float* Wb     = (const float*)d_in[4];
    const float* bb     = (const float*)d_in[5];
    const float* Wgate  = (const float*)d_in[6];
    const float* bgate  = (const float*)d_in[7];
    const float* Ws     = (const float*)d_in[8];
    const float* bs     = (const float*)d_in[9];
    const float* Wg     = (const float*)d_in[10];
    const float* bg     = (const float*)d_in[11];
    float* out = (float*)d_out;

    cudaFuncSetAttribute(ntm_head_kernel,
                         cudaFuncAttributeMaxDynamicSharedMemorySize,
                         SMEM_BYTES);

    ntm_head_kernel<<<BB, NT, SMEM_BYTES>>>(memory, cstate, prevw,
                                            Wk, Wb, bb, Wgate, bgate,
                                            Ws, bs, Wg, bg, out);
}

// round 7
// speedup vs baseline: 1.1600x; 1.1600x over previous
#include <cuda_runtime.h>
#include <cstdint>
#include <math.h>

#define BB 512
#define GRID (BB / 2)             // 256 CTAs, 2 batches each
#define MM 4096
#define DD 64
#define CC 256
#define NT 256                    // threads per block (8 warps)
#define NW (NT / 32)
#define TILE 128                  // memory rows per tile (32 KB data)
#define NTILES (MM / TILE)        // 32
#define ROWPAD 17                 // float4 per padded row (16 data + 1 pad)
#define BUFF4 (TILE * ROWPAD)     // float4 per buffer = 2176
#define LD_PER_THR (TILE * (DD/4) / NT)   // 8
#define RPT (MM / NT)             // 16
#define EPSF 1e-8f
#define LOG2E 1.442695040888963f

// dyn smem floats: 2 stream buffers + SA + misc  (~87 KB) -> 2 CTAs/SM
#define SMEM_FLOATS (2 * BUFF4 * 4 + MM + CC + DD + 8 + 6 + 6)
#define SMEM_BYTES (SMEM_FLOATS * 4)

// ---- software exp2: FADD/FMA only ----
__device__ __forceinline__ float fast_exp2(float y) {
    y = fmaxf(y, -250.0f);
    float t = y + 12582912.0f;
    int   ni = __float_as_int(t) - 0x4B400000;
    float f = y - (t - 12582912.0f);
    float p = 1.52527338e-5f;
    p = fmaf(p, f, 1.54035304e-4f);
    p = fmaf(p, f, 1.33335581e-3f);
    p = fmaf(p, f, 9.61812911e-3f);
    p = fmaf(p, f, 5.55041087e-2f);
    p = fmaf(p, f, 2.40226507e-1f);
    p = fmaf(p, f, 6.93147181e-1f);
    p = fmaf(p, f, 1.0f);
    int n1 = ni >> 1;
    int n2 = ni - n1;
    float s1 = __int_as_float((n1 + 127) << 23);
    float s2 = __int_as_float((n2 + 127) << 23);
    return p * s1 * s2;
}

__device__ __forceinline__ float fast_log2(float x) {
    int ix = __float_as_int(x);
    int e = ((ix >> 23) & 0xff) - 127;
    float m = __int_as_float((ix & 0x007fffff) | 0x3f800000);
    if (m > 1.41421356f) { m *= 0.5f; e += 1; }
    float s = __fdividef(m - 1.0f, m + 1.0f);
    float s2 = s * s;
    float p = 0.111111111f;
    p = fmaf(p, s2, 0.142857143f);
    p = fmaf(p, s2, 0.2f);
    p = fmaf(p, s2, 0.333333333f);
    p = fmaf(p, s2, 1.0f);
    float lnm = 2.0f * s * p;
    return (float)e + lnm * LOG2E;
}

__device__ __forceinline__ float fast_exp(float z) { return fast_exp2(z * LOG2E); }
__device__ __forceinline__ float fast_pow(float x, float g) { return fast_exp2(g * fast_log2(x)); }

__device__ __forceinline__ float blockReduceSum(float v, float* sh) {
    int lane = threadIdx.x & 31, wid = threadIdx.x >> 5;
    #pragma unroll
    for (int o = 16; o; o >>= 1) v += __shfl_xor_sync(0xffffffffu, v, o);
    __syncthreads();
    if (lane == 0) sh[wid] = v;
    __syncthreads();
    if (wid == 0) {
        float x = (lane < NW) ? sh[lane] : 0.0f;
        #pragma unroll
        for (int o = NW / 2; o; o >>= 1) x += __shfl_xor_sync(0xffffffffu, x, o);
        if (lane == 0) sh[0] = x;
    }
    __syncthreads();
    return sh[0];
}

__device__ __forceinline__ float blockReduceMax(float v, float* sh) {
    int lane = threadIdx.x & 31, wid = threadIdx.x >> 5;
    #pragma unroll
    for (int o = 16; o; o >>= 1) v = fmaxf(v, __shfl_xor_sync(0xffffffffu, v, o));
    __syncthreads();
    if (lane == 0) sh[wid] = v;
    __syncthreads();
    if (wid == 0) {
        float x = (lane < NW) ? sh[lane] : -INFINITY;
        #pragma unroll
        for (int o = NW / 2; o; o >>= 1) x = fmaxf(x, __shfl_xor_sync(0xffffffffu, x, o));
        if (lane == 0) sh[0] = x;
    }
    __syncthreads();
    return sh[0];
}

__device__ __forceinline__ void prefetch_tile(const float4* gsrc_tile,
                                              uint32_t dst_base_u32, int tid) {
    #pragma unroll
    for (int k = 0; k < LD_PER_THR; k++) {
        int lin = tid + k * NT;             // 0..2047, coalesced
        int r = lin >> 4;
        int c = lin & 15;
        uint32_t dst = dst_base_u32 + (uint32_t)(r * ROWPAD + c) * 16u;
        asm volatile("cp.async.cg.shared.global [%0], [%1], 16;\n"
                     :: "r"(dst), "l"(gsrc_tile + lin) : "memory");
    }
    asm volatile("cp.async.commit_group;\n" ::: "memory");
}

__global__ __launch_bounds__(NT)
void ntm_head_kernel(
    const float* __restrict__ memory,     // (B, M, D)
    const float* __restrict__ cstate,     // (B, C)
    const float* __restrict__ prevw,      // (B, M)
    const float* __restrict__ Wk,         // (C, D)
    const float* __restrict__ Wb,
    const float* __restrict__ bb,
    const float* __restrict__ Wgate,
    const float* __restrict__ bgate,
    const float* __restrict__ Ws,
    const float* __restrict__ bs,
    const float* __restrict__ Wg,
    const float* __restrict__ bg,
    float* __restrict__ out)              // (B, M)
{
    extern __shared__ float smem[];
    float4* buf     = reinterpret_cast<float4*>(smem);      // 2 * BUFF4
    float*  SA      = smem + 2 * BUFF4 * 4;                 // MM
    float*  sh_cs   = SA + MM;                              // CC
    float*  sh_qn   = sh_cs + CC;                           // DD
    float*  sh_red  = sh_qn + DD;                           // 8
    float*  sh_scal = sh_red + 8;                           // 6
    float*  sh_par  = sh_scal + 6;                          // 6

    const int tid  = threadIdx.x;
    const int lane = tid & 31;
    const int wid  = tid >> 5;

    const uint32_t buf_u32 = (uint32_t)__cvta_generic_to_shared(buf);
    const float4*  mem4    = reinterpret_cast<const float4*>(memory);

    // ---- pre-issue tiles 0 and 1 of the first batch ----
    {
        const float4* mb = mem4 + (size_t)blockIdx.x * MM * (DD / 4);
        prefetch_tile(mb, buf_u32, tid);
        prefetch_tile(mb + (size_t)TILE * (DD / 4), buf_u32 + (uint32_t)BUFF4 * 16u, tid);
    }

    for (int bi = 0; bi < 2; bi++) {
        const int b = blockIdx.x + bi * GRID;
        const float4* memb = mem4 + (size_t)b * MM * (DD / 4);

        // ================= preamble (overlaps in-flight DMA) =================
        sh_cs[tid] = cstate[(size_t)b * CC + tid];
        __syncthreads();

        if (tid < DD) {
            float acc = 0.0f;
            #pragma unroll 8
            for (int c = 0; c < CC; c++) acc = fmaf(sh_cs[c], Wk[c * DD + tid], acc);
            sh_qn[tid] = acc;
        }
        if (wid >= 2) {
            int s = wid - 2;
            float acc = 0.0f;
            if (s < 3) {
                const float* W = (s == 0) ? Wb : (s == 1) ? Wgate : Wg;
                for (int c = lane; c < CC; c += 32) acc = fmaf(sh_cs[c], W[c], acc);
            } else {
                int col = s - 3;
                for (int c = lane; c < CC; c += 32) acc = fmaf(sh_cs[c], Ws[c * 3 + col], acc);
            }
            #pragma unroll
            for (int o = 16; o; o >>= 1) acc += __shfl_xor_sync(0xffffffffu, acc, o);
            if (lane == 0) sh_scal[s] = acc;
        }
        __syncthreads();

        if (wid == 0) {
            float a = sh_qn[lane], c = sh_qn[lane + 32];
            float v = a * a + c * c;
            #pragma unroll
            for (int o = 16; o; o >>= 1) v += __shfl_xor_sync(0xffffffffu, v, o);
            float inv = 1.0f / (sqrtf(v) + EPSF);
            sh_qn[lane]      = a * inv;
            sh_qn[lane + 32] = c * inv;
        }
        if (tid == 32) {
            sh_par[0] = log1pf(__expf(sh_scal[0] + bb[0])) + 1.0f;            // beta
            sh_par[1] = 1.0f / (1.0f + __expf(-(sh_scal[1] + bgate[0])));     // gate
            sh_par[2] = log1pf(__expf(sh_scal[2] + bg[0])) + 1.0f;            // gamma
            float a0 = sh_scal[3] + bs[0];
            float a1 = sh_scal[4] + bs[1];
            float a2 = sh_scal[5] + bs[2];
            float mx = fmaxf(a0, fmaxf(a1, a2));
            float e0 = __expf(a0 - mx), e1 = __expf(a1 - mx), e2 = __expf(a2 - mx);
            float inv = 1.0f / (e0 + e1 + e2);
            sh_par[3] = e0 * inv; sh_par[4] = e1 * inv; sh_par[5] = e2 * inv;
        }
        __syncthreads();

        // ================= stream loop (tiles 0,1 already in flight) =================
        const float4* qn4 = reinterpret_cast<const float4*>(sh_qn);

        for (int t = 0; t < NTILES; t++) {
            if (t < NTILES - 1) {
                asm volatile("cp.async.wait_group 1;\n" ::: "memory");
            } else {
                asm volatile("cp.async.wait_group 0;\n" ::: "memory");
            }
            __syncthreads();   // tile t visible

            if (tid < TILE) {
                const float4* rowp = buf + (size_t)(t & 1) * BUFF4 + tid * ROWPAD;
                float dot = 0.0f, ss = 0.0f;
                #pragma unroll
                for (int j = 0; j < DD / 4; j++) {
                    float4 v = rowp[j];
                    float4 q = qn4[j];
                    dot = fmaf(v.x, q.x, dot); dot = fmaf(v.y, q.y, dot);
                    dot = fmaf(v.z, q.z, dot); dot = fmaf(v.w, q.w, dot);
                    ss  = fmaf(v.x, v.x, ss);  ss  = fmaf(v.y, v.y, ss);
                    ss  = fmaf(v.z, v.z, ss);  ss  = fmaf(v.w, v.w, ss);
                }
                SA[t * TILE + tid] = dot * rsqrtf(ss);
            }
            __syncthreads();   // compute done: buffer (t&1) reusable

            if (t + 2 < NTILES) {
                prefetch_tile(memb + (size_t)(t + 2) * TILE * (DD / 4),
                              buf_u32 + (uint32_t)(((t + 2) & 1) * BUFF4) * 16u, tid);
            }
        }

        // ---- both buffers free: pre-issue next batch's tiles 0,1 before epilogue ----
        if (bi == 0) {
            const float4* mbn = mem4 + (size_t)(b + GRID) * MM * (DD / 4);
            prefetch_tile(mbn, buf_u32, tid);
            prefetch_tile(mbn + (size_t)TILE * (DD / 4), buf_u32 + (uint32_t)BUFF4 * 16u, tid);
        }

        // ================= epilogue (overlaps next batch's DMA) =================
        const float beta = sh_par[0];
        float lmax = -INFINITY;
        #pragma unroll
        for (int k = 0; k < RPT; k++) lmax = fmaxf(lmax, SA[tid + k * NT]);
        const float smax = blockReduceMax(lmax, sh_red) * beta;

        float lsum = 0.0f;
        #pragma unroll
        for (int k = 0; k < RPT; k++) {
            int m = tid + k * NT;
            float e = fast_exp(fmaf(beta, SA[m], -smax));
            SA[m] = e;
            lsum += e;
        }
        const float invsum = 1.0f / blockReduceSum(lsum, sh_red);

        const float gate = sh_par[1], gate1 = 1.0f - sh_par[1];
        const float* pw = prevw + (size_t)b * MM;
        #pragma unroll
        for (int k = 0; k < RPT; k++) {
            int m = tid + k * NT;
            SA[m] = fmaf(gate, SA[m] * invsum, gate1 * pw[m]);
        }
        __syncthreads();

        const float gamma = sh_par[2];
        const float s0 = sh_par[3], s1 = sh_par[4], s2 = sh_par[5];
        float p[RPT];
        float psum = 0.0f;
        #pragma unroll
        for (int k = 0; k < RPT; k++) {
            int m  = tid + k * NT;
            int ml = (m == 0)      ? MM - 1 : m - 1;
            int mr = (m == MM - 1) ? 0      : m + 1;
            float sv = SA[ml] * s0 + SA[m] * s1 + SA[mr] * s2;
            p[k] = fast_pow(sv + EPSF, gamma);
            psum += p[k];
        }
        psum = blockReduceSum(psum, sh_red);   // internal barrier: SA reads done
        const float invp = 1.0f / (psum + EPSF);

        float* ob = out + (size_t)b * MM;
        #pragma unroll
        for (int k = 0; k < RPT; k++) {
            int m = tid + k * NT;
            ob[m] = p[k] * invp;
        }
        __syncthreads();   // SA/sh_* reusable for next batch
    }
}

extern "C" void kernel_launch(void* const* d_in, const int* in_sizes, int n_in,
                              void* d_out, int out_size) {
    const float* memory = (const float*)d_in[0];
    const float* cstate = (const float*)d_in[1];
    const float* prevw  = (const float*)d_in[2];
    const float* Wk     = (const float*)d_in[3];
    const float* Wb     = (const float*)d_in[4];
    const float* bb     = (const float*)d_in[5];
    const float* Wgate  = (const float*)d_in[6];
    const float* bgate  = (const float*)d_in[7];
    const float* Ws     = (const float*)d_in[8];
    const float* bs     = (const float*)d_in[9];
    const float* Wg     = (const float*)d_in[10];
    const float* bg     = (const float*)d_in[11];
    float* out = (float*)d_out;

    static int smem_set = 0;
    if (!smem_set) {
        cudaFuncSetAttribute(ntm_head_kernel,
                             cudaFuncAttributeMaxDynamicSharedMemorySize,
                             SMEM_BYTES);
        smem_set = 1;
    }

    ntm_head_kernel<<<GRID, NT, SMEM_BYTES>>>(memory, cstate, prevw,
                                              Wk, Wb, bb, Wgate, bgate,
                                              Ws, bs, Wg, bg, out);
}